// round 14
// baseline (speedup 1.0000x reference)
#include <cuda_runtime.h>
#include <cstdint>

#define B_SZ   32
#define RESN   100
#define ITERS  1000
#define KSPLIT 16

typedef unsigned long long ull;

// Jacobi: 250 threads, each owns 4 rows x 10 cols in registers.
// SMEM per buffer (words): TOP 3000 | BOT 3000 | CL 1000 | CR 1000 = 8000
#define SLOTW  12
#define OFF_BOT 3000
#define OFF_CL  6000
#define OFF_CR  7000
#define BUFW    8000

// -------- scratch (device globals; no allocation allowed) ----------
__device__ float g_h3[B_SZ * 512];
__device__ float g_part[KSPLIT * B_SZ * 10000];

// ---------------------- f32x2 helpers ------------------------------
__device__ __forceinline__ ull pack2(float lo, float hi) {
    ull r; unsigned a = __float_as_uint(lo), b = __float_as_uint(hi);
    asm("mov.b64 %0, {%1,%2};" : "=l"(r) : "r"(a), "r"(b));
    return r;
}
__device__ __forceinline__ float lo2(ull v) {
    unsigned a, b;
    asm("mov.b64 {%0,%1}, %2;" : "=r"(a), "=r"(b) : "l"(v));
    return __uint_as_float(a);
}
__device__ __forceinline__ float hi2(ull v) {
    unsigned a, b;
    asm("mov.b64 {%0,%1}, %2;" : "=r"(a), "=r"(b) : "l"(v));
    return __uint_as_float(b);
}
__device__ __forceinline__ ull shift_pair(ull a, ull b) {   // (hi a, lo b)
    unsigned a0, a1, b0, b1;
    asm("mov.b64 {%0,%1}, %2;" : "=r"(a0), "=r"(a1) : "l"(a));
    asm("mov.b64 {%0,%1}, %2;" : "=r"(b0), "=r"(b1) : "l"(b));
    ull r;
    asm("mov.b64 %0, {%1,%2};" : "=l"(r) : "r"(a1), "r"(b0));
    return r;
}
__device__ __forceinline__ ull fma2(ull a, ull b, ull c) {
    ull d;
    asm("fma.rn.f32x2 %0, %1, %2, %3;" : "=l"(d) : "l"(a), "l"(b), "l"(c));
    return d;
}
__device__ __forceinline__ ull mul2(ull a, ull b) {
    ull d;
    asm("mul.rn.f32x2 %0, %1, %2;" : "=l"(d) : "l"(a), "l"(b));
    return d;
}

// ------------- fused MLP layers 1..3 (one CTA per sample) ----------
__global__ __launch_bounds__(256) void mlp123_kernel(
    const float* __restrict__ pores,
    const float* __restrict__ W1, const float* __restrict__ b1,
    const float* __restrict__ W2, const float* __restrict__ b2,
    const float* __restrict__ W3, const float* __restrict__ b3)
{
    __shared__ float h1[128];
    __shared__ float h2[256];
    __shared__ float pr[25];
    int b = blockIdx.x;
    int tid = threadIdx.x;

    if (tid < 25) pr[tid] = pores[b * 25 + tid];
    __syncthreads();

    // fc1: 128 outputs, 25 deep
    if (tid < 128) {
        float acc = b1[tid];
#pragma unroll
        for (int k = 0; k < 25; k++)
            acc = fmaf(pr[k], W1[k * 128 + tid], acc);
        h1[tid] = fmaxf(acc, 0.0f);
    }
    __syncthreads();

    // fc2: 256 outputs, 128 deep
    {
        float acc = b2[tid];
#pragma unroll 8
        for (int k = 0; k < 128; k++)
            acc = fmaf(h1[k], W2[k * 256 + tid], acc);
        h2[tid] = fmaxf(acc, 0.0f);
    }
    __syncthreads();

    // fc3: 512 outputs, 256 deep (2 per thread)
#pragma unroll
    for (int jj = 0; jj < 2; jj++) {
        int j = tid + jj * 256;
        float acc = b3[j];
#pragma unroll 8
        for (int k = 0; k < 256; k++)
            acc = fmaf(h2[k], W3[k * 512 + j], acc);
        g_h3[b * 512 + j] = fmaxf(acc, 0.0f);
    }
}

// ---------------- fc4 stage 1: split-K partial sums ----------------
// grid (40, KSPLIT): each thread computes outputs o and o+5000,
// so every h3 LDS feeds 2 FMAs (kernel is LDS-issue bound).
__global__ __launch_bounds__(128) void fc4_partial_kernel(
    const float* __restrict__ W)     // [512,10000]
{
    __shared__ float h3s[B_SZ * 32];
    int k0 = blockIdx.y * 32;
    for (int i = threadIdx.x; i < B_SZ * 32; i += blockDim.x) {
        int q = i >> 5, kk = i & 31;
        h3s[i] = g_h3[q * 512 + k0 + kk];
    }
    __syncthreads();

    int o = blockIdx.x * blockDim.x + threadIdx.x;   // [0,5120)
    if (o >= 5000) return;
    int o2 = o + 5000;

    float accA[B_SZ], accB[B_SZ];
#pragma unroll
    for (int q = 0; q < B_SZ; q++) { accA[q] = 0.0f; accB[q] = 0.0f; }

#pragma unroll 4
    for (int kk = 0; kk < 32; kk += 2) {
        float wA0 = W[(k0 + kk + 0) * 10000 + o];
        float wB0 = W[(k0 + kk + 0) * 10000 + o2];
        float wA1 = W[(k0 + kk + 1) * 10000 + o];
        float wB1 = W[(k0 + kk + 1) * 10000 + o2];
#pragma unroll
        for (int q = 0; q < B_SZ; q++) {
            float h0 = h3s[q * 32 + kk + 0];
            float h1v = h3s[q * 32 + kk + 1];
            accA[q] = fmaf(h0, wA0, accA[q]);
            accB[q] = fmaf(h0, wB0, accB[q]);
            accA[q] = fmaf(h1v, wA1, accA[q]);
            accB[q] = fmaf(h1v, wB1, accB[q]);
        }
    }

    float* dst = g_part + blockIdx.y * (B_SZ * 10000);
#pragma unroll
    for (int q = 0; q < B_SZ; q++) {
        dst[q * 10000 + o]  = accA[q];
        dst[q * 10000 + o2] = accB[q];
    }
}

// -------- fc4 stage 2: reduce + bias + residual + clamp ------------
__global__ __launch_bounds__(128) void fc4_final_kernel(
    const float* __restrict__ bias,
    const float* __restrict__ pores,
    float* __restrict__ cond)
{
    int o = blockIdx.x * blockDim.x + threadIdx.x;
    if (o >= RESN * RESN) return;
    int i = o / RESN, j = o % RESN;
    int pidx = (i / 20) * 5 + (j / 20);
    int q = blockIdx.y;
    float s = bias[o];
#pragma unroll
    for (int p = 0; p < KSPLIT; p++)
        s += g_part[p * (B_SZ * 10000) + q * 10000 + o];
    float base = 1.0f - pores[q * 25 + pidx];
    cond[q * 10000 + o] = fmaxf(s + base, 0.01f);
}

// ---------- Jacobi: 4x10 register tiles, early top-row store --------
// band = tid/10 (25 bands of 4 rows), tcol = tid%10 (10 strips of 10 cols).
// Identical to the R8 winner except the NEW top row is stored right
// after row 0 is computed, so those STS drain during the remaining
// ~60 FFMA2 instead of stacking up at the barrier (drain = 36+36*n_STS).
__global__ __launch_bounds__(256, 1)
void jacobi_kernel(const float* __restrict__ cond,   // [32,10000]
                   float* __restrict__ kappa)        // [32]
{
    extern __shared__ float sm[];
    float* partial = sm + 2 * BUFW;    // 10 floats

    int b = blockIdx.x;
    const float* k = cond + b * 10000;
    int tid  = threadIdx.x;            // 0..249, all active
    int band = tid / 10;               // 0..24
    int tcol = tid % 10;               // 0..9
    int r0 = band * 4, c0 = tcol * 10;

    const ull ONE2 = 0x3F8000003F800000ULL;

    ull cN[4][5], cS[4][5], cW[4][5], cE[4][5], P[4][5];

    // ---- coefficients (registers, computed once) ----
#pragma unroll
    for (int i = 0; i < 4; i++) {
        int rg = r0 + i;
        int rm = (rg == 0)  ? 0  : rg - 1;
        int rp = (rg == 99) ? 99 : rg + 1;
        float fN[10], fS[10], fW[10], fE[10];
#pragma unroll
        for (int j = 0; j < 10; j++) {
            int c  = c0 + j;
            int cm = (c == 0)  ? 0  : c - 1;
            int cp = (c == 99) ? 99 : c + 1;
            float kc = k[rg * 100 + c];
            float kn = 0.5f * (kc + k[rm * 100 + c]);
            float ks = 0.5f * (kc + k[rp * 100 + c]);
            float kw = 0.5f * (kc + k[rg * 100 + cm]);
            float ke = 0.5f * (kc + k[rg * 100 + cp]);
            float inv = 1.0f / (kn + ks + kw + ke + 1e-12f);
            fN[j] = kn * inv; fS[j] = ks * inv;
            fW[j] = kw * inv; fE[j] = ke * inv;
        }
#pragma unroll
        for (int p = 0; p < 5; p++) {
            cN[i][p] = pack2(fN[2*p], fN[2*p+1]);
            cS[i][p] = pack2(fS[2*p], fS[2*p+1]);
            cW[i][p] = pack2(fW[2*p], fW[2*p+1]);
            cE[i][p] = pack2(fE[2*p], fE[2*p+1]);
        }
    }

    // ---- initial field + buffer-0 perimeter ----
#pragma unroll
    for (int i = 0; i < 4; i++) {
        float tv = 1.0f - (float)(r0 + i) * (1.0f / 99.0f);
#pragma unroll
        for (int p = 0; p < 5; p++) P[i][p] = pack2(tv, tv);
    }
    {
        float* tp = sm + tid * SLOTW;
        ulonglong2 v; v.x = P[0][0]; v.y = P[0][1];
        *reinterpret_cast<ulonglong2*>(tp) = v;
        v.x = P[0][2]; v.y = P[0][3];
        *reinterpret_cast<ulonglong2*>(tp + 4) = v;
        *reinterpret_cast<ull*>(tp + 8) = P[0][4];
        float* bt = sm + OFF_BOT + tid * SLOTW;
        v.x = P[3][0]; v.y = P[3][1];
        *reinterpret_cast<ulonglong2*>(bt) = v;
        v.x = P[3][2]; v.y = P[3][3];
        *reinterpret_cast<ulonglong2*>(bt + 4) = v;
        *reinterpret_cast<ull*>(bt + 8) = P[3][4];
        *reinterpret_cast<float4*>(sm + OFF_CL + tid * 4) =
            make_float4(lo2(P[0][0]), lo2(P[1][0]), lo2(P[2][0]), lo2(P[3][0]));
        *reinterpret_cast<float4*>(sm + OFF_CR + tid * 4) =
            make_float4(hi2(P[0][4]), hi2(P[1][4]), hi2(P[2][4]), hi2(P[3][4]));
    }
    __syncthreads();

    int cur = 0;
    for (int it = 0; it < ITERS; ++it) {
        const float* C  = sm + cur * BUFW;
        float*       Nx = sm + (cur ^ 1) * BUFW;

        // ---- halo loads (OLD values; clamp addr, override value) ----
        const float* np = C + OFF_BOT + ((band == 0)  ? tid : tid - 10) * SLOTW;
        const float* sp = C +            ((band == 24) ? tid : tid + 10) * SLOTW;
        ulonglong2 nA = *reinterpret_cast<const ulonglong2*>(np);
        ulonglong2 nB = *reinterpret_cast<const ulonglong2*>(np + 4);
        ull        nC = *reinterpret_cast<const ull*>(np + 8);
        ulonglong2 sA = *reinterpret_cast<const ulonglong2*>(sp);
        ulonglong2 sB = *reinterpret_cast<const ulonglong2*>(sp + 4);
        ull        sC = *reinterpret_cast<const ull*>(sp + 8);
        float4 wf = *reinterpret_cast<const float4*>(
            C + OFF_CR + ((tcol == 0) ? tid : tid - 1) * 4);
        float4 ef = *reinterpret_cast<const float4*>(
            C + OFF_CL + ((tcol == 9) ? tid : tid + 1) * 4);

        if (band == 0)  { nA.x = ONE2; nA.y = ONE2; nB.x = ONE2; nB.y = ONE2; nC = ONE2; }
        if (band == 24) { sA.x = 0; sA.y = 0; sB.x = 0; sB.y = 0; sC = 0; }
        float west[4] = {wf.x, wf.y, wf.z, wf.w};
        float east[4] = {ef.x, ef.y, ef.z, ef.w};

        ull pn0 = nA.x, pn1 = nA.y, pn2 = nB.x, pn3 = nB.y, pn4 = nC;
#pragma unroll
        for (int i = 0; i < 4; i++) {
            ull o0 = P[i][0], o1 = P[i][1], o2 = P[i][2], o3 = P[i][3], o4 = P[i][4];
            ull s0, s1, s2, s3, s4;
            if (i < 3) { s0 = P[i+1][0]; s1 = P[i+1][1]; s2 = P[i+1][2];
                         s3 = P[i+1][3]; s4 = P[i+1][4]; }
            else       { s0 = sA.x; s1 = sA.y; s2 = sB.x; s3 = sB.y; s4 = sC; }

            float left  = (tcol == 0) ? lo2(o0) : west[i];
            float right = (tcol == 9) ? hi2(o4) : east[i];

            ull W0 = pack2(left, lo2(o0));
            ull E0 = shift_pair(o0, o1);
            ull E1 = shift_pair(o1, o2);
            ull E2 = shift_pair(o2, o3);
            ull E3 = shift_pair(o3, o4);
            ull E4 = pack2(hi2(o4), right);

            P[i][0] = fma2(cN[i][0], pn0, fma2(cS[i][0], s0,
                      fma2(cW[i][0], W0, mul2(cE[i][0], E0))));
            P[i][1] = fma2(cN[i][1], pn1, fma2(cS[i][1], s1,
                      fma2(cW[i][1], E0, mul2(cE[i][1], E1))));
            P[i][2] = fma2(cN[i][2], pn2, fma2(cS[i][2], s2,
                      fma2(cW[i][2], E1, mul2(cE[i][2], E2))));
            P[i][3] = fma2(cN[i][3], pn3, fma2(cS[i][3], s3,
                      fma2(cW[i][3], E2, mul2(cE[i][3], E3))));
            P[i][4] = fma2(cN[i][4], pn4, fma2(cS[i][4], s4,
                      fma2(cW[i][4], E3, mul2(cE[i][4], E4))));

            pn0 = o0; pn1 = o1; pn2 = o2; pn3 = o3; pn4 = o4;

            // EARLY publish of the new top row: these 3 STS retire
            // while rows 1-3 are still computing, shrinking the
            // in-flight STS count at the barrier.
            if (i == 0) {
                float* tp = Nx + tid * SLOTW;
                ulonglong2 v; v.x = P[0][0]; v.y = P[0][1];
                *reinterpret_cast<ulonglong2*>(tp) = v;
                v.x = P[0][2]; v.y = P[0][3];
                *reinterpret_cast<ulonglong2*>(tp + 4) = v;
                *reinterpret_cast<ull*>(tp + 8) = P[0][4];
            }
        }

        // ---- publish remaining perimeter (bot row + cols) ----
        float* bt = Nx + OFF_BOT + tid * SLOTW;
        ulonglong2 v; v.x = P[3][0]; v.y = P[3][1];
        *reinterpret_cast<ulonglong2*>(bt) = v;
        v.x = P[3][2]; v.y = P[3][3];
        *reinterpret_cast<ulonglong2*>(bt + 4) = v;
        *reinterpret_cast<ull*>(bt + 8) = P[3][4];
        *reinterpret_cast<float4*>(Nx + OFF_CL + tid * 4) =
            make_float4(lo2(P[0][0]), lo2(P[1][0]), lo2(P[2][0]), lo2(P[3][0]));
        *reinterpret_cast<float4*>(Nx + OFF_CR + tid * 4) =
            make_float4(hi2(P[0][4]), hi2(P[1][4]), hi2(P[2][4]), hi2(P[3][4]));

        __syncthreads();
        cur ^= 1;
    }

    // kappa = 2 * sum_c k[0,c] * (1 - T[0,c]); band 0 holds global row 0
    if (band == 0) {
        float p = 0.0f;
#pragma unroll
        for (int m = 0; m < 5; m++) {
            p += k[c0 + 2*m]     * (1.0f - lo2(P[0][m]));
            p += k[c0 + 2*m + 1] * (1.0f - hi2(P[0][m]));
        }
        partial[tcol] = p;
    }
    __syncthreads();
    if (tid == 0) {
        float sum = 0.0f;
#pragma unroll
        for (int q = 0; q < 10; q++) sum += partial[q];
        kappa[b] = 2.0f * sum;
    }
}

// --------------------------- launcher ------------------------------
extern "C" void kernel_launch(void* const* d_in, const int* in_sizes, int n_in,
                              void* d_out, int out_size) {
    const float* pores = (const float*)d_in[0];
    const float* W1 = (const float*)d_in[1];
    const float* b1 = (const float*)d_in[2];
    const float* W2 = (const float*)d_in[3];
    const float* b2 = (const float*)d_in[4];
    const float* W3 = (const float*)d_in[5];
    const float* b3 = (const float*)d_in[6];
    const float* W4 = (const float*)d_in[7];
    const float* b4 = (const float*)d_in[8];

    float* out   = (float*)d_out;
    float* kappa = out;          // [32]
    float* cond  = out + B_SZ;   // [32,100,100]

    const int SMEM_JAC = (2 * BUFW + 16) * sizeof(float);  // ~64.1 KB
    cudaFuncSetAttribute(jacobi_kernel, cudaFuncAttributeMaxDynamicSharedMemorySize, SMEM_JAC);

    mlp123_kernel<<<B_SZ, 256>>>(pores, W1, b1, W2, b2, W3, b3);
    dim3 g4(40, KSPLIT);
    fc4_partial_kernel<<<g4, 128>>>(W4);
    dim3 g5((10000 + 127) / 128, B_SZ);
    fc4_final_kernel<<<g5, 128>>>(b4, pores, cond);
    jacobi_kernel<<<B_SZ, 250, SMEM_JAC>>>(cond, kappa);
}

// round 15
// speedup vs baseline: 1.3289x; 1.3289x over previous
#include <cuda_runtime.h>
#include <cstdint>

#define B_SZ   32
#define RESN   100
#define ITERS  1000
#define KSPLIT 16

typedef unsigned long long ull;

// Jacobi: 250 threads, each owns 4 rows x 10 cols in registers.
// SMEM per buffer (words): TOP 3000 | BOT 3000 | CL 1000 | CR 1000 = 8000
#define SLOTW  12
#define OFF_BOT 3000
#define OFF_CL  6000
#define OFF_CR  7000
#define BUFW    8000

// -------- scratch (device globals; no allocation allowed) ----------
__device__ float g_h3[B_SZ * 512];
__device__ float g_part[KSPLIT * B_SZ * 10000];

// ---------------------- f32x2 helpers ------------------------------
__device__ __forceinline__ ull pack2(float lo, float hi) {
    ull r; unsigned a = __float_as_uint(lo), b = __float_as_uint(hi);
    asm("mov.b64 %0, {%1,%2};" : "=l"(r) : "r"(a), "r"(b));
    return r;
}
__device__ __forceinline__ float lo2(ull v) {
    unsigned a, b;
    asm("mov.b64 {%0,%1}, %2;" : "=r"(a), "=r"(b) : "l"(v));
    return __uint_as_float(a);
}
__device__ __forceinline__ float hi2(ull v) {
    unsigned a, b;
    asm("mov.b64 {%0,%1}, %2;" : "=r"(a), "=r"(b) : "l"(v));
    return __uint_as_float(b);
}
__device__ __forceinline__ ull shift_pair(ull a, ull b) {   // (hi a, lo b)
    unsigned a0, a1, b0, b1;
    asm("mov.b64 {%0,%1}, %2;" : "=r"(a0), "=r"(a1) : "l"(a));
    asm("mov.b64 {%0,%1}, %2;" : "=r"(b0), "=r"(b1) : "l"(b));
    ull r;
    asm("mov.b64 %0, {%1,%2};" : "=l"(r) : "r"(a1), "r"(b0));
    return r;
}
__device__ __forceinline__ ull fma2(ull a, ull b, ull c) {
    ull d;
    asm("fma.rn.f32x2 %0, %1, %2, %3;" : "=l"(d) : "l"(a), "l"(b), "l"(c));
    return d;
}
__device__ __forceinline__ ull mul2(ull a, ull b) {
    ull d;
    asm("mul.rn.f32x2 %0, %1, %2;" : "=l"(d) : "l"(a), "l"(b));
    return d;
}

// ------------- fused MLP layers 1..3 (one CTA per sample) ----------
__global__ __launch_bounds__(256) void mlp123_kernel(
    const float* __restrict__ pores,
    const float* __restrict__ W1, const float* __restrict__ b1,
    const float* __restrict__ W2, const float* __restrict__ b2,
    const float* __restrict__ W3, const float* __restrict__ b3)
{
    __shared__ float h1[128];
    __shared__ float h2[256];
    __shared__ float pr[25];
    int b = blockIdx.x;
    int tid = threadIdx.x;

    if (tid < 25) pr[tid] = pores[b * 25 + tid];
    __syncthreads();

    if (tid < 128) {
        float acc = b1[tid];
#pragma unroll
        for (int k = 0; k < 25; k++)
            acc = fmaf(pr[k], W1[k * 128 + tid], acc);
        h1[tid] = fmaxf(acc, 0.0f);
    }
    __syncthreads();

    {
        float acc = b2[tid];
#pragma unroll 8
        for (int k = 0; k < 128; k++)
            acc = fmaf(h1[k], W2[k * 256 + tid], acc);
        h2[tid] = fmaxf(acc, 0.0f);
    }
    __syncthreads();

#pragma unroll
    for (int jj = 0; jj < 2; jj++) {
        int j = tid + jj * 256;
        float acc = b3[j];
#pragma unroll 8
        for (int k = 0; k < 256; k++)
            acc = fmaf(h2[k], W3[k * 512 + j], acc);
        g_h3[b * 512 + j] = fmaxf(acc, 0.0f);
    }
}

// ---------------- fc4 stage 1: split-K partial sums ----------------
// grid (40, KSPLIT): each thread computes outputs o and o+5000,
// so every h3 LDS feeds 2 FMAs.
__global__ __launch_bounds__(128) void fc4_partial_kernel(
    const float* __restrict__ W)     // [512,10000]
{
    __shared__ float h3s[B_SZ * 32];
    int k0 = blockIdx.y * 32;
    for (int i = threadIdx.x; i < B_SZ * 32; i += blockDim.x) {
        int q = i >> 5, kk = i & 31;
        h3s[i] = g_h3[q * 512 + k0 + kk];
    }
    __syncthreads();

    int o = blockIdx.x * blockDim.x + threadIdx.x;   // [0,5120)
    if (o >= 5000) return;
    int o2 = o + 5000;

    float accA[B_SZ], accB[B_SZ];
#pragma unroll
    for (int q = 0; q < B_SZ; q++) { accA[q] = 0.0f; accB[q] = 0.0f; }

#pragma unroll 4
    for (int kk = 0; kk < 32; kk += 2) {
        float wA0 = W[(k0 + kk + 0) * 10000 + o];
        float wB0 = W[(k0 + kk + 0) * 10000 + o2];
        float wA1 = W[(k0 + kk + 1) * 10000 + o];
        float wB1 = W[(k0 + kk + 1) * 10000 + o2];
#pragma unroll
        for (int q = 0; q < B_SZ; q++) {
            float h0 = h3s[q * 32 + kk + 0];
            float h1v = h3s[q * 32 + kk + 1];
            accA[q] = fmaf(h0, wA0, accA[q]);
            accB[q] = fmaf(h0, wB0, accB[q]);
            accA[q] = fmaf(h1v, wA1, accA[q]);
            accB[q] = fmaf(h1v, wB1, accB[q]);
        }
    }

    float* dst = g_part + blockIdx.y * (B_SZ * 10000);
#pragma unroll
    for (int q = 0; q < B_SZ; q++) {
        dst[q * 10000 + o]  = accA[q];
        dst[q * 10000 + o2] = accB[q];
    }
}

// -------- fc4 stage 2: reduce + bias + residual + clamp ------------
__global__ __launch_bounds__(128) void fc4_final_kernel(
    const float* __restrict__ bias,
    const float* __restrict__ pores,
    float* __restrict__ cond)
{
    int o = blockIdx.x * blockDim.x + threadIdx.x;
    if (o >= RESN * RESN) return;
    int i = o / RESN, j = o % RESN;
    int pidx = (i / 20) * 5 + (j / 20);
    int q = blockIdx.y;
    float s = bias[o];
#pragma unroll
    for (int p = 0; p < KSPLIT; p++)
        s += g_part[p * (B_SZ * 10000) + q * 10000 + o];
    float base = 1.0f - pores[q * 25 + pidx];
    cond[q * 10000 + o] = fmaxf(s + base, 0.01f);
}

// ---------- Jacobi: 4x10 register tiles, 250 threads (R8 exact) -----
// band = tid/10 (25 bands of 4 rows), tcol = tid%10 (10 strips of 10 cols).
// T tile P[4][5] as f32x2 pairs. Per iter only the perimeter moves
// through SMEM: top row, bottom row (12-word slots, 48B stride ->
// conflict-free), left col, right col (dense float4 arrays).
__global__ __launch_bounds__(256, 1)
void jacobi_kernel(const float* __restrict__ cond,   // [32,10000]
                   float* __restrict__ kappa)        // [32]
{
    extern __shared__ float sm[];
    float* partial = sm + 2 * BUFW;    // 10 floats

    int b = blockIdx.x;
    const float* k = cond + b * 10000;
    int tid  = threadIdx.x;            // 0..249, all active
    int band = tid / 10;               // 0..24
    int tcol = tid % 10;               // 0..9
    int r0 = band * 4, c0 = tcol * 10;

    const ull ONE2 = 0x3F8000003F800000ULL;

    ull cN[4][5], cS[4][5], cW[4][5], cE[4][5], P[4][5];

    // ---- coefficients (registers, computed once) ----
#pragma unroll
    for (int i = 0; i < 4; i++) {
        int rg = r0 + i;
        int rm = (rg == 0)  ? 0  : rg - 1;
        int rp = (rg == 99) ? 99 : rg + 1;
        float fN[10], fS[10], fW[10], fE[10];
#pragma unroll
        for (int j = 0; j < 10; j++) {
            int c  = c0 + j;
            int cm = (c == 0)  ? 0  : c - 1;
            int cp = (c == 99) ? 99 : c + 1;
            float kc = k[rg * 100 + c];
            float kn = 0.5f * (kc + k[rm * 100 + c]);
            float ks = 0.5f * (kc + k[rp * 100 + c]);
            float kw = 0.5f * (kc + k[rg * 100 + cm]);
            float ke = 0.5f * (kc + k[rg * 100 + cp]);
            float inv = 1.0f / (kn + ks + kw + ke + 1e-12f);
            fN[j] = kn * inv; fS[j] = ks * inv;
            fW[j] = kw * inv; fE[j] = ke * inv;
        }
#pragma unroll
        for (int p = 0; p < 5; p++) {
            cN[i][p] = pack2(fN[2*p], fN[2*p+1]);
            cS[i][p] = pack2(fS[2*p], fS[2*p+1]);
            cW[i][p] = pack2(fW[2*p], fW[2*p+1]);
            cE[i][p] = pack2(fE[2*p], fE[2*p+1]);
        }
    }

    // ---- initial field + buffer-0 perimeter ----
#pragma unroll
    for (int i = 0; i < 4; i++) {
        float tv = 1.0f - (float)(r0 + i) * (1.0f / 99.0f);
#pragma unroll
        for (int p = 0; p < 5; p++) P[i][p] = pack2(tv, tv);
    }
    {
        float* tp = sm + tid * SLOTW;
        ulonglong2 v; v.x = P[0][0]; v.y = P[0][1];
        *reinterpret_cast<ulonglong2*>(tp) = v;
        v.x = P[0][2]; v.y = P[0][3];
        *reinterpret_cast<ulonglong2*>(tp + 4) = v;
        *reinterpret_cast<ull*>(tp + 8) = P[0][4];
        float* bt = sm + OFF_BOT + tid * SLOTW;
        v.x = P[3][0]; v.y = P[3][1];
        *reinterpret_cast<ulonglong2*>(bt) = v;
        v.x = P[3][2]; v.y = P[3][3];
        *reinterpret_cast<ulonglong2*>(bt + 4) = v;
        *reinterpret_cast<ull*>(bt + 8) = P[3][4];
        *reinterpret_cast<float4*>(sm + OFF_CL + tid * 4) =
            make_float4(lo2(P[0][0]), lo2(P[1][0]), lo2(P[2][0]), lo2(P[3][0]));
        *reinterpret_cast<float4*>(sm + OFF_CR + tid * 4) =
            make_float4(hi2(P[0][4]), hi2(P[1][4]), hi2(P[2][4]), hi2(P[3][4]));
    }
    __syncthreads();

    int cur = 0;
    for (int it = 0; it < ITERS; ++it) {
        const float* C  = sm + cur * BUFW;
        float*       Nx = sm + (cur ^ 1) * BUFW;

        // ---- halo loads (OLD values; clamp addr, override value) ----
        const float* np = C + OFF_BOT + ((band == 0)  ? tid : tid - 10) * SLOTW;
        const float* sp = C +            ((band == 24) ? tid : tid + 10) * SLOTW;
        ulonglong2 nA = *reinterpret_cast<const ulonglong2*>(np);
        ulonglong2 nB = *reinterpret_cast<const ulonglong2*>(np + 4);
        ull        nC = *reinterpret_cast<const ull*>(np + 8);
        ulonglong2 sA = *reinterpret_cast<const ulonglong2*>(sp);
        ulonglong2 sB = *reinterpret_cast<const ulonglong2*>(sp + 4);
        ull        sC = *reinterpret_cast<const ull*>(sp + 8);
        float4 wf = *reinterpret_cast<const float4*>(
            C + OFF_CR + ((tcol == 0) ? tid : tid - 1) * 4);
        float4 ef = *reinterpret_cast<const float4*>(
            C + OFF_CL + ((tcol == 9) ? tid : tid + 1) * 4);

        if (band == 0)  { nA.x = ONE2; nA.y = ONE2; nB.x = ONE2; nB.y = ONE2; nC = ONE2; }
        if (band == 24) { sA.x = 0; sA.y = 0; sB.x = 0; sB.y = 0; sC = 0; }
        float west[4] = {wf.x, wf.y, wf.z, wf.w};
        float east[4] = {ef.x, ef.y, ef.z, ef.w};

        ull pn0 = nA.x, pn1 = nA.y, pn2 = nB.x, pn3 = nB.y, pn4 = nC;
#pragma unroll
        for (int i = 0; i < 4; i++) {
            ull o0 = P[i][0], o1 = P[i][1], o2 = P[i][2], o3 = P[i][3], o4 = P[i][4];
            ull s0, s1, s2, s3, s4;
            if (i < 3) { s0 = P[i+1][0]; s1 = P[i+1][1]; s2 = P[i+1][2];
                         s3 = P[i+1][3]; s4 = P[i+1][4]; }
            else       { s0 = sA.x; s1 = sA.y; s2 = sB.x; s3 = sB.y; s4 = sC; }

            float left  = (tcol == 0) ? lo2(o0) : west[i];
            float right = (tcol == 9) ? hi2(o4) : east[i];

            ull W0 = pack2(left, lo2(o0));
            ull E0 = shift_pair(o0, o1);
            ull E1 = shift_pair(o1, o2);
            ull E2 = shift_pair(o2, o3);
            ull E3 = shift_pair(o3, o4);
            ull E4 = pack2(hi2(o4), right);

            P[i][0] = fma2(cN[i][0], pn0, fma2(cS[i][0], s0,
                      fma2(cW[i][0], W0, mul2(cE[i][0], E0))));
            P[i][1] = fma2(cN[i][1], pn1, fma2(cS[i][1], s1,
                      fma2(cW[i][1], E0, mul2(cE[i][1], E1))));
            P[i][2] = fma2(cN[i][2], pn2, fma2(cS[i][2], s2,
                      fma2(cW[i][2], E1, mul2(cE[i][2], E2))));
            P[i][3] = fma2(cN[i][3], pn3, fma2(cS[i][3], s3,
                      fma2(cW[i][3], E2, mul2(cE[i][3], E3))));
            P[i][4] = fma2(cN[i][4], pn4, fma2(cS[i][4], s4,
                      fma2(cW[i][4], E3, mul2(cE[i][4], E4))));

            pn0 = o0; pn1 = o1; pn2 = o2; pn3 = o3; pn4 = o4;
        }

        // ---- publish new perimeter ----
        float* tp = Nx + tid * SLOTW;
        ulonglong2 v; v.x = P[0][0]; v.y = P[0][1];
        *reinterpret_cast<ulonglong2*>(tp) = v;
        v.x = P[0][2]; v.y = P[0][3];
        *reinterpret_cast<ulonglong2*>(tp + 4) = v;
        *reinterpret_cast<ull*>(tp + 8) = P[0][4];
        float* bt = Nx + OFF_BOT + tid * SLOTW;
        v.x = P[3][0]; v.y = P[3][1];
        *reinterpret_cast<ulonglong2*>(bt) = v;
        v.x = P[3][2]; v.y = P[3][3];
        *reinterpret_cast<ulonglong2*>(bt + 4) = v;
        *reinterpret_cast<ull*>(bt + 8) = P[3][4];
        *reinterpret_cast<float4*>(Nx + OFF_CL + tid * 4) =
            make_float4(lo2(P[0][0]), lo2(P[1][0]), lo2(P[2][0]), lo2(P[3][0]));
        *reinterpret_cast<float4*>(Nx + OFF_CR + tid * 4) =
            make_float4(hi2(P[0][4]), hi2(P[1][4]), hi2(P[2][4]), hi2(P[3][4]));

        __syncthreads();
        cur ^= 1;
    }

    // kappa = 2 * sum_c k[0,c] * (1 - T[0,c]); band 0 holds global row 0
    if (band == 0) {
        float p = 0.0f;
#pragma unroll
        for (int m = 0; m < 5; m++) {
            p += k[c0 + 2*m]     * (1.0f - lo2(P[0][m]));
            p += k[c0 + 2*m + 1] * (1.0f - hi2(P[0][m]));
        }
        partial[tcol] = p;
    }
    __syncthreads();
    if (tid == 0) {
        float sum = 0.0f;
#pragma unroll
        for (int q = 0; q < 10; q++) sum += partial[q];
        kappa[b] = 2.0f * sum;
    }
}

// --------------------------- launcher ------------------------------
extern "C" void kernel_launch(void* const* d_in, const int* in_sizes, int n_in,
                              void* d_out, int out_size) {
    const float* pores = (const float*)d_in[0];
    const float* W1 = (const float*)d_in[1];
    const float* b1 = (const float*)d_in[2];
    const float* W2 = (const float*)d_in[3];
    const float* b2 = (const float*)d_in[4];
    const float* W3 = (const float*)d_in[5];
    const float* b3 = (const float*)d_in[6];
    const float* W4 = (const float*)d_in[7];
    const float* b4 = (const float*)d_in[8];

    float* out   = (float*)d_out;
    float* kappa = out;          // [32]
    float* cond  = out + B_SZ;   // [32,100,100]

    const int SMEM_JAC = (2 * BUFW + 16) * sizeof(float);  // ~64.1 KB
    cudaFuncSetAttribute(jacobi_kernel, cudaFuncAttributeMaxDynamicSharedMemorySize, SMEM_JAC);

    mlp123_kernel<<<B_SZ, 256>>>(pores, W1, b1, W2, b2, W3, b3);
    dim3 g4(40, KSPLIT);
    fc4_partial_kernel<<<g4, 128>>>(W4);
    dim3 g5((10000 + 127) / 128, B_SZ);
    fc4_final_kernel<<<g5, 128>>>(b4, pores, cond);
    jacobi_kernel<<<B_SZ, 250, SMEM_JAC>>>(cond, kappa);
}